// round 12
// baseline (speedup 1.0000x reference)
#include <cuda_runtime.h>
#include <cstdint>

#define TT 2048
#define BB 128
#define HH 200
// Block 1024, grid 64 (2 batches per CTA).
// Compute: tid < 1000: kc = tid/200 (0..4), j = tid%200.
//   Thread holds W_hh[j, 40kc : 40kc+40) once (20 u64 = 40 regs) and runs TWO
//   accumulator chains (batch A and B) off the same W registers.
// Phase B: tid<400 epilogue (A: 0-199, B: 200-399); warp 13 head for out[t-1].

typedef unsigned long long ull;

__device__ __forceinline__ void fma2(ull& acc, ull a, ull b) {
    asm("fma.rn.f32x2 %0, %1, %2, %0;" : "+l"(acc) : "l"(a), "l"(b));
}
__device__ __forceinline__ void unpack2(ull v, float& lo, float& hi) {
    asm("mov.b64 {%0,%1}, %2;" : "=f"(lo), "=f"(hi) : "l"(v));
}
__device__ __forceinline__ float tanh_hw(float x) {
    float r; asm("tanh.approx.f32 %0, %1;" : "=f"(r) : "f"(x));
    return r;
}

__global__ void __launch_bounds__(1024, 1) rnn_kernel(
    const float* __restrict__ x,     // [T, B, 2]
    const float* __restrict__ Wih,   // [H, 2]
    const float* __restrict__ Whh,   // [H, H]
    const float* __restrict__ bih,   // [H]
    const float* __restrict__ bhh,   // [H]
    const float* __restrict__ Wout,  // [1, H]
    const float* __restrict__ bOut,  // [1]
    float* __restrict__ out)         // [T, B, 1]
{
    __shared__ __align__(16) float2 xsmA[TT];      // batch A inputs (16 KB)
    __shared__ __align__(16) float2 xsmB[TT];      // batch B inputs (16 KB)
    __shared__ __align__(16) float  hsmA[2][HH];   // A hidden, double-buffered
    __shared__ __align__(16) float  hsmB[2][HH];   // B hidden, double-buffered
    __shared__ __align__(16) float  partA[1000];   // A partials [kc*200+j]
    __shared__ __align__(16) float  partB[1000];   // B partials
    __shared__ __align__(16) float  wosm[HH];      // Wout staged in smem

    const int tid  = threadIdx.x;
    const int b0   = 2 * blockIdx.x;
    const int b1   = b0 + 1;
    const int kc   = tid / 200;
    const int j    = tid - kc * 200;
    const bool compute = (tid < 1000);

    // Preload both input sequences
    for (int i = tid; i < TT; i += 1024) {
        xsmA[i] = *(const float2*)(x + ((size_t)i * BB + b0) * 2);
        xsmB[i] = *(const float2*)(x + ((size_t)i * BB + b1) * 2);
    }
    if (tid < HH) wosm[tid] = Wout[tid];

    // W_hh[j, 40kc : +40) as 20 packed fp32 pairs (8B-aligned: j*200+40kc even)
    ull wr[20];
    if (compute) {
        const ull* wrow = (const ull*)(Whh + (size_t)j * HH + 40 * kc);
#pragma unroll
        for (int i = 0; i < 20; i++) wr[i] = wrow[i];
    }

    // Epilogue constants for phase-B threads (tid<400), keyed by je = tid%200
    float wih0 = 0.f, wih1 = 0.f, bias = 0.f;
    const int je = (tid < 200) ? tid : tid - 200;
    if (tid < 400) {
        wih0 = Wih[2 * je];
        wih1 = Wih[2 * je + 1];
        bias = bih[je] + bhh[je];
    }
    const float bo = bOut[0];

    // h_0 = 0 for both batches, both buffers
    if (tid < 2 * HH) {
        ((float*)hsmA)[tid] = 0.0f;
        ((float*)hsmB)[tid] = 0.0f;
    }
    __syncthreads();

#pragma unroll 1
    for (int t = 0; t < TT; t++) {
        const int rp = t & 1;   // hsm[rp] = h_{t-1}; phase B writes hsm[rp^1]

        // ---- Phase A: dot partials for both batches
        if (compute) {
            const ulonglong2* hpA = (const ulonglong2*)(&hsmA[rp][40 * kc]);
            const ulonglong2* hpB = (const ulonglong2*)(&hsmB[rp][40 * kc]);
            ull accA = 0ull, accB = 0ull;
#pragma unroll
            for (int i = 0; i < 10; i++) {
                ulonglong2 ha = hpA[i];   // broadcast LDS.128
                ulonglong2 hb = hpB[i];
                fma2(accA, ha.x, wr[2 * i]);
                fma2(accA, ha.y, wr[2 * i + 1]);
                fma2(accB, hb.x, wr[2 * i]);
                fma2(accB, hb.y, wr[2 * i + 1]);
            }
            float a0, a1, c0, c1;
            unpack2(accA, a0, a1);
            unpack2(accB, c0, c1);
            partA[tid] = a0 + a1;
            partB[tid] = c0 + c1;
        }
        __syncthreads();

        // ---- Phase B: reduce + tanh + publish (tid<400); head (warp 13)
        if (tid < 400) {
            const float* part = (tid < 200) ? partA : partB;
            float s = part[je] + part[200 + je] + part[400 + je] +
                      part[600 + je] + part[800 + je];
            float2 xv = (tid < 200) ? xsmA[t] : xsmB[t];
            float pre = fmaf(xv.x, wih0, fmaf(xv.y, wih1, s + bias));
            float h = tanh_hw(pre);
            if (tid < 200) hsmA[rp ^ 1][je] = h;
            else           hsmB[rp ^ 1][je] = h;
        } else if (tid >= 416 && tid < 448 && t > 0) {
            // warp 13: out[t-1] for both batches from hsm[rp] (= h_{t-1})
            const int g    = tid - 416;
            const int l16  = g & 15;
            const float* hv = (g < 16) ? hsmA[rp] : hsmB[rp];
            float acc = 0.0f;
#pragma unroll
            for (int i = 0; i < 13; i++) {
                int idx = l16 + 16 * i;
                if (idx < HH) acc = fmaf(hv[idx], wosm[idx], acc);
            }
#pragma unroll
            for (int off = 8; off; off >>= 1)
                acc += __shfl_xor_sync(0xFFFFFFFFu, acc, off);
            if (l16 == 0)
                out[(size_t)(t - 1) * BB + ((g < 16) ? b0 : b1)] = acc + bo;
        }
        __syncthreads();
    }

    // Final outputs: h_{T-1} lives in hsm[TT & 1] == hsm[0]
    if (tid >= 416 && tid < 448) {
        const int g    = tid - 416;
        const int l16  = g & 15;
        const float* hv = (g < 16) ? hsmA[0] : hsmB[0];
        float acc = 0.0f;
#pragma unroll
        for (int i = 0; i < 13; i++) {
            int idx = l16 + 16 * i;
            if (idx < HH) acc = fmaf(hv[idx], wosm[idx], acc);
        }
#pragma unroll
        for (int off = 8; off; off >>= 1)
            acc += __shfl_xor_sync(0xFFFFFFFFu, acc, off);
        if (l16 == 0)
            out[(size_t)(TT - 1) * BB + ((g < 16) ? b0 : b1)] = acc + bo;
    }
}

extern "C" void kernel_launch(void* const* d_in, const int* in_sizes, int n_in,
                              void* d_out, int out_size) {
    const float* input_seq = (const float*)d_in[0];  // [T,B,2]
    const float* W_ih      = (const float*)d_in[1];  // [H,2]
    const float* W_hh      = (const float*)d_in[2];  // [H,H]
    const float* b_ih      = (const float*)d_in[3];  // [H]
    const float* b_hh      = (const float*)d_in[4];  // [H]
    const float* W_out     = (const float*)d_in[5];  // [1,H]
    const float* b_out     = (const float*)d_in[6];  // [1]
    float* out = (float*)d_out;                      // [T,B,1]

    rnn_kernel<<<BB / 2, 1024>>>(input_seq, W_ih, W_hh, b_ih, b_hh,
                                 W_out, b_out, out);
}

// round 15
// speedup vs baseline: 4.2429x; 4.2429x over previous
#include <cuda_runtime.h>
#include <cstdint>

#define TT 2048
#define BB 128
#define HH 200
#define KS 20     // k-span per chunk (10 chunks x 20 = 200, no padding)
#define NKC 10    // k-chunks
#define NJQ 50    // j-quads (4 j each): 50*4 = 200, no padding
// compute threads: tid = kc*50 + jq, 500 total; block 512 (16 warps)
// warp 8 overlap-region (tid 256-287) doubles as head warp in phase B

typedef unsigned long long ull;

__device__ __forceinline__ void fma2(ull& acc, ull a, ull b) {
    asm("fma.rn.f32x2 %0, %1, %2, %0;" : "+l"(acc) : "l"(a), "l"(b));
}
__device__ __forceinline__ void unpack2(ull v, float& lo, float& hi) {
    asm("mov.b64 {%0,%1}, %2;" : "=f"(lo), "=f"(hi) : "l"(v));
}
__device__ __forceinline__ float tanh_hw(float x) {
    float r; asm("tanh.approx.f32 %0, %1;" : "=f"(r) : "f"(x));
    return r;
}

__global__ void __launch_bounds__(512, 1) rnn_kernel(
    const float* __restrict__ x,     // [T, B, 2]
    const float* __restrict__ Wih,   // [H, 2]
    const float* __restrict__ Whh,   // [H, H]
    const float* __restrict__ bih,   // [H]
    const float* __restrict__ bhh,   // [H]
    const float* __restrict__ Wout,  // [1, H]
    const float* __restrict__ bOut,  // [1]
    float* __restrict__ out)         // [T, B, 1]
{
    __shared__ __align__(16) float2 xsm[TT];        // 16 KB input sequence
    __shared__ __align__(16) float  hsm[2][HH];     // double-buffered hidden
    __shared__ __align__(16) float4 part4[NKC * NJQ]; // per-thread j-quad partials
    __shared__ __align__(16) float  wosm[HH];       // Wout staged

    const int tid = threadIdx.x;
    const int b   = blockIdx.x;
    const int kc  = tid / NJQ;       // 0..9 for compute threads
    const int jq  = tid - kc * NJQ;  // 0..49
    const bool compute = (tid < 500);
    const bool headw   = (tid >= 256 && tid < 288);  // warp 8 in phase B
    const int lane = tid & 31;

    // Preload input sequence for this batch
    for (int i = tid; i < TT; i += 512)
        xsm[i] = *(const float2*)(x + ((size_t)i * BB + b) * 2);
    if (tid < HH) wosm[tid] = Wout[tid];

    // W registers: 4 rows (j = 4jq+r), k-chunk [20kc, 20kc+20) as 10 u64 each.
    // 80 registers of W; each h quad loaded in phase A is reused 4x.
    ull wr[4][10];
    if (compute) {
#pragma unroll
        for (int r = 0; r < 4; r++) {
            const ull* wrow = (const ull*)(Whh + (size_t)(4 * jq + r) * HH + KS * kc);
#pragma unroll
            for (int i = 0; i < 10; i++) wr[r][i] = wrow[i];
        }
    }

    // Epilogue constants (threads 0..199, keyed by j = tid)
    float wih0 = 0.f, wih1 = 0.f, bias = 0.f;
    if (tid < HH) {
        wih0 = Wih[2 * tid];
        wih1 = Wih[2 * tid + 1];
        bias = bih[tid] + bhh[tid];
    }
    const float bo = bOut[0];

    // h_0 = 0 in both buffers
    if (tid < 2 * HH) ((float*)hsm)[tid] = 0.0f;
    __syncthreads();

    // At iteration t: h_t is in hsm[t&1]; phase B writes h_{t+1} = hs[t] into
    // hsm[(t&1)^1]; head warp emits out[t-1] = head(h_t) during phase B.
    auto step = [&](int t, int rp) {
        // ---- Phase A: j-quad x k-chunk partials
        if (compute) {
            const ulonglong2* hp = (const ulonglong2*)(&hsm[rp][KS * kc]); // 80B, 16B-aligned
            ull a0 = 0ull, a1 = 0ull, a2 = 0ull, a3 = 0ull;
#pragma unroll
            for (int i = 0; i < 5; i++) {
                ulonglong2 hv = hp[i];           // one LDS.128, reused 4x below
                fma2(a0, hv.x, wr[0][2 * i]); fma2(a0, hv.y, wr[0][2 * i + 1]);
                fma2(a1, hv.x, wr[1][2 * i]); fma2(a1, hv.y, wr[1][2 * i + 1]);
                fma2(a2, hv.x, wr[2][2 * i]); fma2(a2, hv.y, wr[2][2 * i + 1]);
                fma2(a3, hv.x, wr[3][2 * i]); fma2(a3, hv.y, wr[3][2 * i + 1]);
            }
            float4 p;
            { float lo, hi; unpack2(a0, lo, hi); p.x = lo + hi; }
            { float lo, hi; unpack2(a1, lo, hi); p.y = lo + hi; }
            { float lo, hi; unpack2(a2, lo, hi); p.z = lo + hi; }
            { float lo, hi; unpack2(a3, lo, hi); p.w = lo + hi; }
            part4[tid] = p;   // flat float index: 200*kc + j (j = 4jq+r)
        }
        __syncthreads();

        // ---- Phase B: reduce over 10 k-chunks + tanh + publish (tid<200);
        //               head warp reduces h_t (stable in hsm[rp]) -> out[t-1]
        if (tid < HH) {
            const float* pf = (const float*)part4;
            float s = 0.0f;
#pragma unroll
            for (int c = 0; c < NKC; c++) s += pf[200 * c + tid];
            float2 xv = xsm[t];
            float pre = fmaf(xv.x, wih0, fmaf(xv.y, wih1, s + bias));
            hsm[rp ^ 1][tid] = tanh_hw(pre);
        } else if (headw && t > 0) {
            const float* hv = hsm[rp];
            float acc = 0.0f;
#pragma unroll
            for (int i = 0; i < 7; i++) {
                int idx = lane + 32 * i;
                if (idx < HH) acc = fmaf(hv[idx], wosm[idx], acc);
            }
#pragma unroll
            for (int off = 16; off; off >>= 1)
                acc += __shfl_xor_sync(0xFFFFFFFFu, acc, off);
            if (lane == 0) out[(size_t)(t - 1) * BB + b] = acc + bo;
        }
        __syncthreads();
    };

#pragma unroll 1
    for (int t = 0; t < TT; t += 2) {
        step(t, 0);
        step(t + 1, 1);
    }

    // Final output: h_{T} chain ended with hs[TT-1] in hsm[0]
    if (headw) {
        const float* hv = hsm[0];
        float acc = 0.0f;
#pragma unroll
        for (int i = 0; i < 7; i++) {
            int idx = lane + 32 * i;
            if (idx < HH) acc = fmaf(hv[idx], wosm[idx], acc);
        }
#pragma unroll
        for (int off = 16; off; off >>= 1)
            acc += __shfl_xor_sync(0xFFFFFFFFu, acc, off);
        if (lane == 0) out[(size_t)(TT - 1) * BB + b] = acc + bo;
    }
}

extern "C" void kernel_launch(void* const* d_in, const int* in_sizes, int n_in,
                              void* d_out, int out_size) {
    const float* input_seq = (const float*)d_in[0];  // [T,B,2]
    const float* W_ih      = (const float*)d_in[1];  // [H,2]
    const float* W_hh      = (const float*)d_in[2];  // [H,H]
    const float* b_ih      = (const float*)d_in[3];  // [H]
    const float* b_hh      = (const float*)d_in[4];  // [H]
    const float* W_out     = (const float*)d_in[5];  // [1,H]
    const float* b_out     = (const float*)d_in[6];  // [1]
    float* out = (float*)d_out;                      // [T,B,1]

    rnn_kernel<<<BB, 512>>>(input_seq, W_ih, W_hh, b_ih, b_hh, W_out, b_out, out);
}